// round 3
// baseline (speedup 1.0000x reference)
#include <cuda_runtime.h>
#include <math.h>
#include <mma.h>

using namespace nvcuda;

#define D   128
#define CH  7
#define NC  8
#define NS  4
#define MAXM  40000
#define MAXET 680000

// ---------------- scratch (static device globals; no allocation) -------------
__device__ int   g_count[MAXM + 1];
__device__ int   g_off[MAXM + 1];
__device__ int   g_cursor[MAXM];
__device__ int   g_csr[MAXET];
__device__ float g_xl[(size_t)MAXM * D];
__device__ float g_xr[(size_t)MAXM * D];
__device__ float g_h [(size_t)MAXM * D];
__device__ float g_h2[(size_t)MAXM * D];
__device__ float g_s1[MAXM * CH];
__device__ float g_s2[MAXM * CH];
__device__ float g_lg[MAXM * CH];

// ---------------- CSR build --------------------------------------------------
__global__ void k_hist(const int* __restrict__ tgt, int E, int M) {
    int stride = gridDim.x * blockDim.x;
    int ET = E + M;
    for (int i = blockIdx.x * blockDim.x + threadIdx.x; i < ET; i += stride) {
        int t = (i < E) ? tgt[i] : (i - E);
        atomicAdd(&g_count[t], 1);
    }
}

__global__ void k_scan(int M) {  // single block, 1024 threads
    __shared__ int sh[1024];
    int tid = threadIdx.x;
    int chunk = (M + 1023) >> 10;
    int beg = tid * chunk;
    int end = min(beg + chunk, M);
    int s = 0;
    for (int i = beg; i < end; i++) s += g_count[i];
    sh[tid] = s;
    __syncthreads();
    for (int o = 1; o < 1024; o <<= 1) {
        int v = (tid >= o) ? sh[tid - o] : 0;
        __syncthreads();
        sh[tid] += v;
        __syncthreads();
    }
    int run = sh[tid] - s;  // exclusive prefix for this chunk
    for (int i = beg; i < end; i++) {
        g_off[i] = run;
        g_cursor[i] = run;
        run += g_count[i];
    }
    if (tid == 1023) g_off[M] = sh[1023];
}

__global__ void k_scatter(const int* __restrict__ src, const int* __restrict__ tgt,
                          int E, int M) {
    int stride = gridDim.x * blockDim.x;
    int ET = E + M;
    for (int i = blockIdx.x * blockDim.x + threadIdx.x; i < ET; i += stride) {
        int t, s;
        if (i < E) { t = tgt[i]; s = src[i]; }
        else       { t = i - E;  s = i - E; }
        int pos = atomicAdd(&g_cursor[t], 1);
        g_csr[pos] = s;
    }
}

// sort each segment ascending in SHARED memory (deterministic CSR order ->
// bitwise-stable fp accumulation downstream). Block covers 128 nodes; their
// combined span (mean ~2176, Poisson) is staged in smem (cap 6144, >40 sigma).
#define SORT_NODES 128
#define SORT_CAP   6144
__global__ void k_sortseg2(int M) {
    __shared__ int sh[SORT_CAP];
    int n0 = blockIdx.x * SORT_NODES;
    if (n0 >= M) return;
    int nEnd = min(n0 + SORT_NODES, M);
    int beg = g_off[n0], end = g_off[nEnd];
    int span = end - beg;
    int tid = threadIdx.x;  // 128
    if (span <= SORT_CAP) {
        for (int i = beg + tid; i < end; i += blockDim.x) sh[i - beg] = g_csr[i];
        __syncthreads();
        int node = n0 + tid;
        if (node < M) {
            int s = g_off[node] - beg, e = g_off[node + 1] - beg;
            for (int i = s + 1; i < e; i++) {
                int v = sh[i]; int j = i - 1;
                while (j >= s && sh[j] > v) { sh[j + 1] = sh[j]; j--; }
                sh[j + 1] = v;
            }
        }
        __syncthreads();
        for (int i = beg + tid; i < end; i += blockDim.x) g_csr[i] = sh[i - beg];
    } else {  // fallback (statistically unreachable)
        int node = n0 + tid;
        if (node < M) {
            int s = g_off[node], e = g_off[node + 1];
            for (int i = s + 1; i < e; i++) {
                int v = g_csr[i]; int j = i - 1;
                while (j >= s && g_csr[j] > v) { g_csr[j + 1] = g_csr[j]; j--; }
                g_csr[j + 1] = v;
            }
        }
    }
}

// ---------------- 3xTF32 tensor-core GEMM -----------------------------------
// C[M,128] = A[M,128] @ W[128,128] + bias.  fp32 operands split hi/lo in tf32;
// 3 MMAs per tile (hi*hi + hi*lo + lo*hi) -> ~2^-22 error, fp32-equivalent.
// Block: 256 threads (8 warps as 2x4), tile 128x128, whole K in smem.
__device__ __forceinline__ float tf32_rna(float x) {
    unsigned u;
    asm("cvt.rna.tf32.f32 %0, %1;" : "=r"(u) : "f"(x));
    return __uint_as_float(u);
}

__global__ void k_gemm_tc(const float* __restrict__ A, const float* __restrict__ W,
                          const float* __restrict__ bias, float* __restrict__ C, int M) {
    extern __shared__ float sm[];
    float* As = sm;                 // [128][132]
    float* Ws = sm + 128 * 132;     // [128][132]
    __shared__ float bsm[128];
    int tid = threadIdx.x;
    int row0 = blockIdx.x * 128;
    if (tid < 128) bsm[tid] = bias[tid];

    {
        int r = tid >> 1, half = tid & 1;
        int row = row0 + r;
        const float* ap = A + (size_t)row * D + half * 64;
        #pragma unroll
        for (int q = 0; q < 16; q++) {
            float4 v = (row < M) ? *(const float4*)(ap + q * 4)
                                 : make_float4(0.f, 0.f, 0.f, 0.f);
            *(float4*)&As[r * 132 + half * 64 + q * 4] = v;
        }
        const float* wp = W + r * D + half * 64;
        #pragma unroll
        for (int q = 0; q < 16; q++)
            *(float4*)&Ws[r * 132 + half * 64 + q * 4] = *(const float4*)(wp + q * 4);
    }
    __syncthreads();

    int w  = tid >> 5;
    int wr = w >> 2, wc = w & 3;   // warp tile: 64 rows x 32 cols

    wmma::fragment<wmma::accumulator, 16, 16, 8, float> acc[4][2];
    #pragma unroll
    for (int m = 0; m < 4; m++)
        #pragma unroll
        for (int n = 0; n < 2; n++) wmma::fill_fragment(acc[m][n], 0.f);

    wmma::fragment<wmma::matrix_a, 16, 16, 8, wmma::precision::tf32, wmma::row_major> ahi[4], alo[4];
    wmma::fragment<wmma::matrix_b, 16, 16, 8, wmma::precision::tf32, wmma::row_major> bhi[2], blo[2];

    #pragma unroll 2
    for (int kk = 0; kk < 16; kk++) {
        int k0 = kk * 8;
        #pragma unroll
        for (int n = 0; n < 2; n++) {
            wmma::load_matrix_sync(bhi[n], &Ws[k0 * 132 + wc * 32 + n * 16], 132);
            #pragma unroll
            for (int i = 0; i < bhi[n].num_elements; i++) {
                float v = bhi[n].x[i], h = tf32_rna(v);
                bhi[n].x[i] = h;
                blo[n].x[i] = tf32_rna(v - h);
            }
        }
        #pragma unroll
        for (int m = 0; m < 4; m++) {
            wmma::load_matrix_sync(ahi[m], &As[(wr * 64 + m * 16) * 132 + k0], 132);
            #pragma unroll
            for (int i = 0; i < ahi[m].num_elements; i++) {
                float v = ahi[m].x[i], h = tf32_rna(v);
                ahi[m].x[i] = h;
                alo[m].x[i] = tf32_rna(v - h);
            }
        }
        #pragma unroll
        for (int m = 0; m < 4; m++)
            #pragma unroll
            for (int n = 0; n < 2; n++) {
                wmma::mma_sync(acc[m][n], ahi[m], blo[n], acc[m][n]);
                wmma::mma_sync(acc[m][n], alo[m], bhi[n], acc[m][n]);
                wmma::mma_sync(acc[m][n], ahi[m], bhi[n], acc[m][n]);
            }
    }
    __syncthreads();  // done reading As/Ws; reuse As as output staging

    #pragma unroll
    for (int m = 0; m < 4; m++)
        #pragma unroll
        for (int n = 0; n < 2; n++)
            wmma::store_matrix_sync(&As[(wr * 64 + m * 16) * 132 + wc * 32 + n * 16],
                                    acc[m][n], 132, wmma::mem_row_major);
    __syncthreads();

    {
        int r = tid >> 1, half = tid & 1;
        int row = row0 + r;
        if (row < M) {
            #pragma unroll
            for (int q = 0; q < 16; q++) {
                int c = half * 64 + q * 4;
                float4 v = *(float4*)&As[r * 132 + c];
                v.x += bsm[c]; v.y += bsm[c + 1]; v.z += bsm[c + 2]; v.w += bsm[c + 3];
                *(float4*)&C[(size_t)row * D + c] = v;
            }
        }
    }
}

// ---------------- GATv2 aggregate, Dout=128: one warp per target node --------
__global__ void k_gat128(const float* __restrict__ xl, const float* __restrict__ xr,
                         const float* __restrict__ att, const float* __restrict__ bias,
                         float* __restrict__ out, int M, float slope) {
    int w = (blockIdx.x * blockDim.x + threadIdx.x) >> 5;
    int lane = threadIdx.x & 31;
    if (w >= M) return;

    float4 xr4 = *(const float4*)(xr + (size_t)w * D + lane * 4);
    float4 at4 = *(const float4*)(att + lane * 4);
    int beg = g_off[w], end = g_off[w + 1];

    float m = -INFINITY, d = 0.f;
    float4 acc = make_float4(0.f, 0.f, 0.f, 0.f);

    for (int e = beg; e < end; e++) {
        int s = g_csr[e];
        float4 a = *(const float4*)(xl + (size_t)s * D + lane * 4);
        float t0 = a.x + xr4.x; t0 = (t0 > 0.f) ? t0 : 0.2f * t0;
        float t1 = a.y + xr4.y; t1 = (t1 > 0.f) ? t1 : 0.2f * t1;
        float t2 = a.z + xr4.z; t2 = (t2 > 0.f) ? t2 : 0.2f * t2;
        float t3 = a.w + xr4.w; t3 = (t3 > 0.f) ? t3 : 0.2f * t3;
        float p = t0 * at4.x + t1 * at4.y + t2 * at4.z + t3 * at4.w;
        #pragma unroll
        for (int o = 16; o; o >>= 1) p += __shfl_xor_sync(0xffffffffu, p, o);

        if (p <= m) {               // warp-uniform branch; common case: no rescale
            float wgt = __expf(p - m);
            d += wgt;
            acc.x += wgt * a.x; acc.y += wgt * a.y;
            acc.z += wgt * a.z; acc.w += wgt * a.w;
        } else {
            float c1 = __expf(m - p);   // first iter: exp(-inf)=0
            d = d * c1 + 1.f;
            acc.x = acc.x * c1 + a.x; acc.y = acc.y * c1 + a.y;
            acc.z = acc.z * c1 + a.z; acc.w = acc.w * c1 + a.w;
            m = p;
        }
    }

    float inv = 1.f / (d + 1e-16f);
    float4 b4 = *(const float4*)(bias + lane * 4);
    float o0 = acc.x * inv + b4.x;
    float o1 = acc.y * inv + b4.y;
    float o2 = acc.z * inv + b4.z;
    float o3 = acc.w * inv + b4.w;
    if (slope > 0.f) {
        o0 = (o0 > 0.f) ? o0 : slope * o0;
        o1 = (o1 > 0.f) ? o1 : slope * o1;
        o2 = (o2 > 0.f) ? o2 : slope * o2;
        o3 = (o3 > 0.f) ? o3 : slope * o3;
    }
    *(float4*)(out + (size_t)w * D + lane * 4) = make_float4(o0, o1, o2, o3);
}

// ---------------- GATv2 aggregate, Dout=7 ------------------------------------
__global__ void k_gat7(const float* __restrict__ xl, const float* __restrict__ xr,
                       const float* __restrict__ att, const float* __restrict__ bias,
                       float* __restrict__ out, int M) {
    int w = (blockIdx.x * blockDim.x + threadIdx.x) >> 5;
    int lane = threadIdx.x & 31;
    if (w >= M) return;

    float xrv = (lane < CH) ? xr[w * CH + lane] : 0.f;
    float atv = (lane < CH) ? att[lane] : 0.f;
    int beg = g_off[w], end = g_off[w + 1];

    float m = -INFINITY, d = 0.f, acc = 0.f;
    for (int e = beg; e < end; e++) {
        int s = g_csr[e];
        float av = (lane < CH) ? xl[s * CH + lane] : 0.f;
        float t = av + xrv; t = (t > 0.f) ? t : 0.2f * t;
        float p = t * atv;
        #pragma unroll
        for (int o = 16; o; o >>= 1) p += __shfl_xor_sync(0xffffffffu, p, o);
        if (p <= m) {
            float wgt = __expf(p - m);
            d += wgt; acc += wgt * av;
        } else {
            float c1 = __expf(m - p);
            d = d * c1 + 1.f;
            acc = acc * c1 + av;
            m = p;
        }
    }
    if (lane < CH)
        out[w * CH + lane] = acc / (d + 1e-16f) + bias[lane];
}

// ---------------- fused dual GEMM: [M,128]@[128,7]x2, smem-staged ------------
__global__ void k_gemm7x2(const float* __restrict__ A,
                          const float* __restrict__ W1, const float* __restrict__ b1,
                          const float* __restrict__ W2, const float* __restrict__ b2,
                          float* __restrict__ C1, float* __restrict__ C2, int M) {
    __shared__ float As[32][132];
    __shared__ float W1s[D * CH], W2s[D * CH];
    __shared__ float b1s[CH], b2s[CH];
    int tid = threadIdx.x;  // 256
    int row0 = blockIdx.x * 32;

    for (int i = tid; i < D * CH; i += 256) { W1s[i] = W1[i]; W2s[i] = W2[i]; }
    if (tid < CH) { b1s[tid] = b1[tid]; b2s[tid] = b2[tid]; }
    {
        int r = tid >> 3, seg = tid & 7;
        int row = row0 + r;
        const float* ap = A + (size_t)row * D + seg * 16;
        #pragma unroll
        for (int q = 0; q < 4; q++) {
            float4 v = (row < M) ? *(const float4*)(ap + q * 4)
                                 : make_float4(0.f, 0.f, 0.f, 0.f);
            *(float4*)&As[r][seg * 16 + q * 4] = v;
        }
    }
    __syncthreads();

    int r = tid >> 3, c = tid & 7;
    int row = row0 + r;
    if (row < M && c < CH) {
        float s1 = 0.f, s2 = 0.f;
        #pragma unroll 16
        for (int k = 0; k < D; k++) {
            float a = As[r][k];
            s1 += a * W1s[k * CH + c];
            s2 += a * W2s[k * CH + c];
        }
        C1[row * CH + c] = s1 + b1s[c];
        C2[row * CH + c] = s2 + b2s[c];
    }
}

// ---------------- actor head: softmax + gumbel + top-4 + sel -----------------
__global__ void k_actor(const float* __restrict__ logits, const float* __restrict__ gu,
                        float* __restrict__ out, int B, int N) {
    __shared__ float shp[4][NC][CH];
    int tid = threadIdx.x;            // 32 threads
    int b = tid >> 3, i = tid & 7;
    bool active = tid < B * NC;
    if (active) {
        int row = b * N + i;
        float l[CH], mx = -INFINITY;
        for (int c = 0; c < CH; c++) { l[c] = logits[row * CH + c]; mx = fmaxf(mx, l[c]); }
        float s = 0.f;
        for (int c = 0; c < CH; c++) { l[c] = expf(l[c] - mx); s += l[c]; }
        for (int c = 0; c < CH; c++) shp[b][i][c] = l[c] / s;
    }
    __syncthreads();
    if (active) {
        float sc[CH];
        for (int c = 0; c < CH; c++) {
            float u = gu[(b * NC + i) * CH + c];
            float g = -logf(-logf(u));
            sc[c] = logf(shp[b][i][c]) + g;
        }
        int base = (b * NC + i) * NS;
        int seloff = B * NC * NS;
        for (int j = 0; j < NS; j++) {
            int best = 0; float bv = -INFINITY;
            for (int c = 0; c < CH; c++)
                if (sc[c] > bv) { bv = sc[c]; best = c; }
            out[base + j] = (float)best;
            out[seloff + base + j] = shp[b][best][j];
            sc[best] = -INFINITY;
        }
    }
}

// ---------------- value head -------------------------------------------------
__global__ void k_value(const float* __restrict__ H, const float* __restrict__ W,
                        const float* __restrict__ b, float* __restrict__ out, int M) {
    int w = (blockIdx.x * blockDim.x + threadIdx.x) >> 5;
    int lane = threadIdx.x & 31;
    if (w >= M) return;
    float4 h4 = *(const float4*)(H + (size_t)w * D + lane * 4);
    float4 w4 = *(const float4*)(W + lane * 4);
    float p = h4.x * w4.x + h4.y * w4.y + h4.z * w4.z + h4.w * w4.w;
    #pragma unroll
    for (int o = 16; o; o >>= 1) p += __shfl_xor_sync(0xffffffffu, p, o);
    if (lane == 0) out[w] = p + b[0];
}

// ---------------- launch -----------------------------------------------------
extern "C" void kernel_launch(void* const* d_in, const int* in_sizes, int n_in,
                              void* d_out, int out_size) {
    const float* x  = (const float*)d_in[0];
    const int*   ei = (const int*)d_in[1];
    const float* gu = (const float*)d_in[2];
    const float* Wp[4][6];
    for (int l = 0; l < 4; l++)
        for (int j = 0; j < 6; j++)
            Wp[l][j] = (const float*)d_in[3 + l * 6 + j];
    const float* fcW = (const float*)d_in[27];
    const float* fcb = (const float*)d_in[28];

    int M = in_sizes[0] / D;
    int E = in_sizes[1] / 2;
    int B = in_sizes[2] / (NC * CH);
    int N = M / B;
    int ET = E + M;
    float* out = (float*)d_out;

    void *pc, *pxl, *pxr, *ph, *ph2, *ps1, *ps2, *plg;
    cudaGetSymbolAddress(&pc,  g_count);
    cudaGetSymbolAddress(&pxl, g_xl);
    cudaGetSymbolAddress(&pxr, g_xr);
    cudaGetSymbolAddress(&ph,  g_h);
    cudaGetSymbolAddress(&ph2, g_h2);
    cudaGetSymbolAddress(&ps1, g_s1);
    cudaGetSymbolAddress(&ps2, g_s2);
    cudaGetSymbolAddress(&plg, g_lg);
    float* xl = (float*)pxl; float* xr = (float*)pxr;
    float* h  = (float*)ph;  float* h2 = (float*)ph2;
    float* s1 = (float*)ps1; float* s2 = (float*)ps2;
    float* lg = (float*)plg;

    const int tb = 256;
    // ---- CSR build (same graph reused by all 4 GAT layers) ----
    cudaMemsetAsync(pc, 0, (size_t)(M + 1) * sizeof(int));
    int gE = (ET + tb - 1) / tb; if (gE > 4096) gE = 4096;
    k_hist<<<gE, tb>>>(ei + E, E, M);
    k_scan<<<1, 1024>>>(M);
    k_scatter<<<gE, tb>>>(ei, ei + E, E, M);
    k_sortseg2<<<(M + SORT_NODES - 1) / SORT_NODES, SORT_NODES>>>(M);

    // ---- GEMM config ----
    size_t smem_tc = 2 * 128 * 132 * sizeof(float);  // 135168 B
    cudaFuncSetAttribute(k_gemm_tc, cudaFuncAttributeMaxDynamicSharedMemorySize, (int)smem_tc);
    int gg = (M + 127) / 128;
    int gw = (M * 32 + tb - 1) / tb;
    int g32 = (M + 31) / 32;

    // ---- actor path ----
    k_gemm_tc<<<gg, tb, smem_tc>>>(x, Wp[0][0], Wp[0][1], xl, M);
    k_gemm_tc<<<gg, tb, smem_tc>>>(x, Wp[0][2], Wp[0][3], xr, M);
    k_gat128<<<gw, tb>>>(xl, xr, Wp[0][4], Wp[0][5], h, M, 0.01f);
    k_gemm7x2<<<g32, tb>>>(h, Wp[1][0], Wp[1][1], Wp[1][2], Wp[1][3], s1, s2, M);
    k_gat7<<<gw, tb>>>(s1, s2, Wp[1][4], Wp[1][5], lg, M);
    k_actor<<<1, 32>>>(lg, gu, out, B, N);

    // ---- critic path ----
    k_gemm_tc<<<gg, tb, smem_tc>>>(x, Wp[2][0], Wp[2][1], xl, M);
    k_gemm_tc<<<gg, tb, smem_tc>>>(x, Wp[2][2], Wp[2][3], xr, M);
    k_gat128<<<gw, tb>>>(xl, xr, Wp[2][4], Wp[2][5], h2, M, 0.01f);
    k_gemm_tc<<<gg, tb, smem_tc>>>(h2, Wp[3][0], Wp[3][1], xl, M);
    k_gemm_tc<<<gg, tb, smem_tc>>>(h2, Wp[3][2], Wp[3][3], xr, M);
    k_gat128<<<gw, tb>>>(xl, xr, Wp[3][4], Wp[3][5], h, M, 0.f);
    k_value<<<gw, tb>>>(h, fcW, fcb, out + 2 * B * NC * NS, M);
}

// round 5
// speedup vs baseline: 1.4633x; 1.4633x over previous
#include <cuda_runtime.h>
#include <cuda_bf16.h>
#include <math.h>
#include <mma.h>

using namespace nvcuda;

#define D   128
#define CH  7
#define NC  8
#define NS  4
#define MAXM  40000
#define MAXET 680000

// ---------------- scratch (static device globals; no allocation) -------------
__device__ int   g_count[MAXM + 1];
__device__ int   g_off[MAXM + 1];
__device__ int   g_cursor[MAXM];
__device__ int   g_csr[MAXET];
__device__ float g_xl[(size_t)MAXM * D];
__device__ float g_xr[(size_t)MAXM * D];
__device__ float g_h [(size_t)MAXM * D];
__device__ float g_h2[(size_t)MAXM * D];
__device__ float g_s1[MAXM * CH];
__device__ float g_s2[MAXM * CH];
__device__ float g_lg[MAXM * CH];

// ---------------- CSR build --------------------------------------------------
__global__ void k_hist(const int* __restrict__ tgt, int E, int M) {
    int stride = gridDim.x * blockDim.x;
    int ET = E + M;
    for (int i = blockIdx.x * blockDim.x + threadIdx.x; i < ET; i += stride) {
        int t = (i < E) ? tgt[i] : (i - E);
        atomicAdd(&g_count[t], 1);
    }
}

__global__ void k_scan(int M) {  // single block, 1024 threads
    __shared__ int sh[1024];
    int tid = threadIdx.x;
    int chunk = (M + 1023) >> 10;
    int beg = tid * chunk;
    int end = min(beg + chunk, M);
    int s = 0;
    for (int i = beg; i < end; i++) s += g_count[i];
    sh[tid] = s;
    __syncthreads();
    for (int o = 1; o < 1024; o <<= 1) {
        int v = (tid >= o) ? sh[tid - o] : 0;
        __syncthreads();
        sh[tid] += v;
        __syncthreads();
    }
    int run = sh[tid] - s;  // exclusive prefix for this chunk
    for (int i = beg; i < end; i++) {
        g_off[i] = run;
        g_cursor[i] = run;
        run += g_count[i];
    }
    if (tid == 1023) g_off[M] = sh[1023];
}

__global__ void k_scatter(const int* __restrict__ src, const int* __restrict__ tgt,
                          int E, int M) {
    int stride = gridDim.x * blockDim.x;
    int ET = E + M;
    for (int i = blockIdx.x * blockDim.x + threadIdx.x; i < ET; i += stride) {
        int t, s;
        if (i < E) { t = tgt[i]; s = src[i]; }
        else       { t = i - E;  s = i - E; }
        int pos = atomicAdd(&g_cursor[t], 1);
        g_csr[pos] = s;
    }
}

// sort each segment ascending in SHARED memory (deterministic CSR order ->
// bitwise-stable fp accumulation downstream).
#define SORT_NODES 128
#define SORT_CAP   6144
__global__ void k_sortseg2(int M) {
    __shared__ int sh[SORT_CAP];
    int n0 = blockIdx.x * SORT_NODES;
    if (n0 >= M) return;
    int nEnd = min(n0 + SORT_NODES, M);
    int beg = g_off[n0], end = g_off[nEnd];
    int span = end - beg;
    int tid = threadIdx.x;  // 128
    if (span <= SORT_CAP) {
        for (int i = beg + tid; i < end; i += blockDim.x) sh[i - beg] = g_csr[i];
        __syncthreads();
        int node = n0 + tid;
        if (node < M) {
            int s = g_off[node] - beg, e = g_off[node + 1] - beg;
            for (int i = s + 1; i < e; i++) {
                int v = sh[i]; int j = i - 1;
                while (j >= s && sh[j] > v) { sh[j + 1] = sh[j]; j--; }
                sh[j + 1] = v;
            }
        }
        __syncthreads();
        for (int i = beg + tid; i < end; i += blockDim.x) g_csr[i] = sh[i - beg];
    } else {  // fallback (statistically unreachable)
        int node = n0 + tid;
        if (node < M) {
            int s = g_off[node], e = g_off[node + 1];
            for (int i = s + 1; i < e; i++) {
                int v = g_csr[i]; int j = i - 1;
                while (j >= s && g_csr[j] > v) { g_csr[j + 1] = g_csr[j]; j--; }
                g_csr[j + 1] = v;
            }
        }
    }
}

// ---------------- bf16x3 tensor-core dual GEMM -------------------------------
// Computes C1 = A@W1+b1 and C2 = A@W2+b2 in one block pass.
// fp32 operands pre-split ONCE into bf16 hi/lo in smem (error ~2^-18/product);
// mainloop is pure ldmatrix+HMMA, 3 passes: ah*bh + ah*bl + al*bh.
#define LDB 136  // bf16 leading dim (128 + 8 pad)
#define LDC 132  // fp32 staging leading dim

__device__ __forceinline__ void split_store4(float4 v, __nv_bfloat16* hi,
                                             __nv_bfloat16* lo, int idx) {
    __nv_bfloat16 h0 = __float2bfloat16(v.x), h1 = __float2bfloat16(v.y),
                  h2 = __float2bfloat16(v.z), h3 = __float2bfloat16(v.w);
    float l0 = v.x - __bfloat162float(h0), l1 = v.y - __bfloat162float(h1),
          l2 = v.z - __bfloat162float(h2), l3 = v.w - __bfloat162float(h3);
    __nv_bfloat162 hp0 = __halves2bfloat162(h0, h1), hp1 = __halves2bfloat162(h2, h3);
    uint2 hv; hv.x = *(unsigned*)&hp0; hv.y = *(unsigned*)&hp1;
    *(uint2*)&hi[idx] = hv;
    __nv_bfloat162 lp0 = __floats2bfloat162_rn(l0, l1), lp1 = __floats2bfloat162_rn(l2, l3);
    uint2 lv; lv.x = *(unsigned*)&lp0; lv.y = *(unsigned*)&lp1;
    *(uint2*)&lo[idx] = lv;
}

__global__ void k_gemm2_bf16(const float* __restrict__ A,
                             const float* __restrict__ W1, const float* __restrict__ b1,
                             float* __restrict__ C1,
                             const float* __restrict__ W2, const float* __restrict__ b2,
                             float* __restrict__ C2, int M) {
    extern __shared__ char smraw[];
    __nv_bfloat16* Ahi = (__nv_bfloat16*)smraw;
    __nv_bfloat16* Alo = Ahi + 128 * LDB;
    __nv_bfloat16* Whi = Alo + 128 * LDB;
    __nv_bfloat16* Wlo = Whi + 128 * LDB;
    float* Cs = (float*)Whi;  // 128*132*4 = 67584 <= 2*128*136*2 = 69632
    __shared__ float bs1[128], bs2[128];

    int tid = threadIdx.x;       // 256
    int row0 = blockIdx.x * 128;
    if (tid < 128) { bs1[tid] = b1[tid]; bs2[tid] = b2[tid]; }

    int r = tid >> 1, half = tid & 1;
    int cbase = half * 64;

    // ---- fill A hi/lo (once) ----
    {
        int row = row0 + r;
        const float* ap = A + (size_t)row * D + cbase;
        #pragma unroll
        for (int q = 0; q < 16; q++) {
            float4 v = (row < M) ? *(const float4*)(ap + q * 4)
                                 : make_float4(0.f, 0.f, 0.f, 0.f);
            split_store4(v, Ahi, Alo, r * LDB + cbase + q * 4);
        }
    }

    int w  = tid >> 5;
    int wr = w >> 2, wc = w & 3;   // warp tile: 64 rows x 32 cols

    #pragma unroll
    for (int pass = 0; pass < 2; pass++) {
        const float* W = pass ? W2 : W1;
        float* C       = pass ? C2 : C1;
        float* bs      = pass ? bs2 : bs1;

        // ---- fill W hi/lo ----
        {
            const float* wp = W + r * D + cbase;
            #pragma unroll
            for (int q = 0; q < 16; q++)
                split_store4(*(const float4*)(wp + q * 4), Whi, Wlo,
                             r * LDB + cbase + q * 4);
        }
        __syncthreads();

        wmma::fragment<wmma::accumulator, 16, 16, 16, float> acc[4][2];
        #pragma unroll
        for (int m = 0; m < 4; m++)
            #pragma unroll
            for (int n = 0; n < 2; n++) wmma::fill_fragment(acc[m][n], 0.f);

        wmma::fragment<wmma::matrix_a, 16, 16, 16, __nv_bfloat16, wmma::row_major> ah[4], al[4];
        wmma::fragment<wmma::matrix_b, 16, 16, 16, __nv_bfloat16, wmma::row_major> bh[2], bl[2];

        #pragma unroll
        for (int kk = 0; kk < 8; kk++) {
            int k0 = kk * 16;
            #pragma unroll
            for (int n = 0; n < 2; n++) {
                wmma::load_matrix_sync(bh[n], &Whi[k0 * LDB + wc * 32 + n * 16], LDB);
                wmma::load_matrix_sync(bl[n], &Wlo[k0 * LDB + wc * 32 + n * 16], LDB);
            }
            #pragma unroll
            for (int m = 0; m < 4; m++) {
                wmma::load_matrix_sync(ah[m], &Ahi[(wr * 64 + m * 16) * LDB + k0], LDB);
                wmma::load_matrix_sync(al[m], &Alo[(wr * 64 + m * 16) * LDB + k0], LDB);
            }
            #pragma unroll
            for (int m = 0; m < 4; m++)
                #pragma unroll
                for (int n = 0; n < 2; n++) {
                    wmma::mma_sync(acc[m][n], ah[m], bl[n], acc[m][n]);
                    wmma::mma_sync(acc[m][n], al[m], bh[n], acc[m][n]);
                    wmma::mma_sync(acc[m][n], ah[m], bh[n], acc[m][n]);
                }
        }
        __syncthreads();  // all warps done reading Whi/Wlo -> safe to overlay Cs

        #pragma unroll
        for (int m = 0; m < 4; m++)
            #pragma unroll
            for (int n = 0; n < 2; n++)
                wmma::store_matrix_sync(&Cs[(wr * 64 + m * 16) * LDC + wc * 32 + n * 16],
                                        acc[m][n], LDC, wmma::mem_row_major);
        __syncthreads();

        {
            int row = row0 + r;
            if (row < M) {
                #pragma unroll
                for (int q = 0; q < 16; q++) {
                    int c = cbase + q * 4;
                    float4 v = *(float4*)&Cs[r * LDC + c];
                    v.x += bs[c]; v.y += bs[c + 1]; v.z += bs[c + 2]; v.w += bs[c + 3];
                    *(float4*)&C[(size_t)row * D + c] = v;
                }
            }
        }
        __syncthreads();  // done reading Cs before next pass refills W region
    }
}

// ---------------- GATv2 aggregate, Dout=128: one warp per target node --------
__global__ void k_gat128(const float* __restrict__ xl, const float* __restrict__ xr,
                         const float* __restrict__ att, const float* __restrict__ bias,
                         float* __restrict__ out, int M, float slope) {
    int w = (blockIdx.x * blockDim.x + threadIdx.x) >> 5;
    int lane = threadIdx.x & 31;
    if (w >= M) return;

    float4 xr4 = *(const float4*)(xr + (size_t)w * D + lane * 4);
    float4 at4 = *(const float4*)(att + lane * 4);
    int beg = g_off[w], end = g_off[w + 1];

    float m = -INFINITY, d = 0.f;
    float4 acc = make_float4(0.f, 0.f, 0.f, 0.f);

    for (int e = beg; e < end; e++) {
        int s = g_csr[e];
        float4 a = *(const float4*)(xl + (size_t)s * D + lane * 4);
        float t0 = a.x + xr4.x; t0 = (t0 > 0.f) ? t0 : 0.2f * t0;
        float t1 = a.y + xr4.y; t1 = (t1 > 0.f) ? t1 : 0.2f * t1;
        float t2 = a.z + xr4.z; t2 = (t2 > 0.f) ? t2 : 0.2f * t2;
        float t3 = a.w + xr4.w; t3 = (t3 > 0.f) ? t3 : 0.2f * t3;
        float p = t0 * at4.x + t1 * at4.y + t2 * at4.z + t3 * at4.w;
        #pragma unroll
        for (int o = 16; o; o >>= 1) p += __shfl_xor_sync(0xffffffffu, p, o);

        if (p <= m) {               // warp-uniform branch; common case: no rescale
            float wgt = __expf(p - m);
            d += wgt;
            acc.x += wgt * a.x; acc.y += wgt * a.y;
            acc.z += wgt * a.z; acc.w += wgt * a.w;
        } else {
            float c1 = __expf(m - p);   // first iter: exp(-inf)=0
            d = d * c1 + 1.f;
            acc.x = acc.x * c1 + a.x; acc.y = acc.y * c1 + a.y;
            acc.z = acc.z * c1 + a.z; acc.w = acc.w * c1 + a.w;
            m = p;
        }
    }

    float inv = 1.f / (d + 1e-16f);
    float4 b4 = *(const float4*)(bias + lane * 4);
    float o0 = acc.x * inv + b4.x;
    float o1 = acc.y * inv + b4.y;
    float o2 = acc.z * inv + b4.z;
    float o3 = acc.w * inv + b4.w;
    if (slope > 0.f) {
        o0 = (o0 > 0.f) ? o0 : slope * o0;
        o1 = (o1 > 0.f) ? o1 : slope * o1;
        o2 = (o2 > 0.f) ? o2 : slope * o2;
        o3 = (o3 > 0.f) ? o3 : slope * o3;
    }
    *(float4*)(out + (size_t)w * D + lane * 4) = make_float4(o0, o1, o2, o3);
}

// ---------------- GATv2 aggregate, Dout=7 ------------------------------------
__global__ void k_gat7(const float* __restrict__ xl, const float* __restrict__ xr,
                       const float* __restrict__ att, const float* __restrict__ bias,
                       float* __restrict__ out, int M) {
    int w = (blockIdx.x * blockDim.x + threadIdx.x) >> 5;
    int lane = threadIdx.x & 31;
    if (w >= M) return;

    float xrv = (lane < CH) ? xr[w * CH + lane] : 0.f;
    float atv = (lane < CH) ? att[lane] : 0.f;
    int beg = g_off[w], end = g_off[w + 1];

    float m = -INFINITY, d = 0.f, acc = 0.f;
    for (int e = beg; e < end; e++) {
        int s = g_csr[e];
        float av = (lane < CH) ? xl[s * CH + lane] : 0.f;
        float t = av + xrv; t = (t > 0.f) ? t : 0.2f * t;
        float p = t * atv;
        #pragma unroll
        for (int o = 16; o; o >>= 1) p += __shfl_xor_sync(0xffffffffu, p, o);
        if (p <= m) {
            float wgt = __expf(p - m);
            d += wgt; acc += wgt * av;
        } else {
            float c1 = __expf(m - p);
            d = d * c1 + 1.f;
            acc = acc * c1 + av;
            m = p;
        }
    }
    if (lane < CH)
        out[w * CH + lane] = acc / (d + 1e-16f) + bias[lane];
}

// ---------------- fused dual GEMM: [M,128]@[128,7]x2, smem-staged ------------
__global__ void k_gemm7x2(const float* __restrict__ A,
                          const float* __restrict__ W1, const float* __restrict__ b1,
                          const float* __restrict__ W2, const float* __restrict__ b2,
                          float* __restrict__ C1, float* __restrict__ C2, int M) {
    __shared__ float As[32][132];
    __shared__ float W1s[D * CH], W2s[D * CH];
    __shared__ float b1s[CH], b2s[CH];
    int tid = threadIdx.x;  // 256
    int row0 = blockIdx.x * 32;

    for (int i = tid; i < D * CH; i += 256) { W1s[i] = W1[i]; W2s[i] = W2[i]; }
    if (tid < CH) { b1s[tid] = b1[tid]; b2s[tid] = b2[tid]; }
    {
        int r = tid >> 3, seg = tid & 7;
        int row = row0 + r;
        const float* ap = A + (size_t)row * D + seg * 16;
        #pragma unroll
        for (int q = 0; q < 4; q++) {
            float4 v = (row < M) ? *(const float4*)(ap + q * 4)
                                 : make_float4(0.f, 0.f, 0.f, 0.f);
            *(float4*)&As[r][seg * 16 + q * 4] = v;
        }
    }
    __syncthreads();

    int r = tid >> 3, c = tid & 7;
    int row = row0 + r;
    if (row < M && c < CH) {
        float s1 = 0.f, s2 = 0.f;
        #pragma unroll 16
        for (int k = 0; k < D; k++) {
            float a = As[r][k];
            s1 += a * W1s[k * CH + c];
            s2 += a * W2s[k * CH + c];
        }
        C1[row * CH + c] = s1 + b1s[c];
        C2[row * CH + c] = s2 + b2s[c];
    }
}

// ---------------- actor head: softmax + gumbel + top-4 + sel -----------------
__global__ void k_actor(const float* __restrict__ logits, const float* __restrict__ gu,
                        float* __restrict__ out, int B, int N) {
    __shared__ float shp[4][NC][CH];
    int tid = threadIdx.x;            // 32 threads
    int b = tid >> 3, i = tid & 7;
    bool active = tid < B * NC;
    if (active) {
        int row = b * N + i;
        float l[CH], mx = -INFINITY;
        for (int c = 0; c < CH; c++) { l[c] = logits[row * CH + c]; mx = fmaxf(mx, l[c]); }
        float s = 0.f;
        for (int c = 0; c < CH; c++) { l[c] = expf(l[c] - mx); s += l[c]; }
        for (int c = 0; c < CH; c++) shp[b][i][c] = l[c] / s;
    }
    __syncthreads();
    if (active) {
        float sc[CH];
        for (int c = 0; c < CH; c++) {
            float u = gu[(b * NC + i) * CH + c];
            float g = -logf(-logf(u));
            sc[c] = logf(shp[b][i][c]) + g;
        }
        int base = (b * NC + i) * NS;
        int seloff = B * NC * NS;
        for (int j = 0; j < NS; j++) {
            int best = 0; float bv = -INFINITY;
            for (int c = 0; c < CH; c++)
                if (sc[c] > bv) { bv = sc[c]; best = c; }
            out[base + j] = (float)best;
            out[seloff + base + j] = shp[b][best][j];
            sc[best] = -INFINITY;
        }
    }
}

// ---------------- value head -------------------------------------------------
__global__ void k_value(const float* __restrict__ H, const float* __restrict__ W,
                        const float* __restrict__ b, float* __restrict__ out, int M) {
    int w = (blockIdx.x * blockDim.x + threadIdx.x) >> 5;
    int lane = threadIdx.x & 31;
    if (w >= M) return;
    float4 h4 = *(const float4*)(H + (size_t)w * D + lane * 4);
    float4 w4 = *(const float4*)(W + lane * 4);
    float p = h4.x * w4.x + h4.y * w4.y + h4.z * w4.z + h4.w * w4.w;
    #pragma unroll
    for (int o = 16; o; o >>= 1) p += __shfl_xor_sync(0xffffffffu, p, o);
    if (lane == 0) out[w] = p + b[0];
}

// ---------------- launch -----------------------------------------------------
extern "C" void kernel_launch(void* const* d_in, const int* in_sizes, int n_in,
                              void* d_out, int out_size) {
    const float* x  = (const float*)d_in[0];
    const int*   ei = (const int*)d_in[1];
    const float* gu = (const float*)d_in[2];
    const float* Wp[4][6];
    for (int l = 0; l < 4; l++)
        for (int j = 0; j < 6; j++)
            Wp[l][j] = (const float*)d_in[3 + l * 6 + j];
    const float* fcW = (const float*)d_in[27];
    const float* fcb = (const float*)d_in[28];

    int M = in_sizes[0] / D;
    int E = in_sizes[1] / 2;
    int B = in_sizes[2] / (NC * CH);
    int N = M / B;
    int ET = E + M;
    float* out = (float*)d_out;

    void *pc, *pxl, *pxr, *ph, *ph2, *ps1, *ps2, *plg;
    cudaGetSymbolAddress(&pc,  g_count);
    cudaGetSymbolAddress(&pxl, g_xl);
    cudaGetSymbolAddress(&pxr, g_xr);
    cudaGetSymbolAddress(&ph,  g_h);
    cudaGetSymbolAddress(&ph2, g_h2);
    cudaGetSymbolAddress(&ps1, g_s1);
    cudaGetSymbolAddress(&ps2, g_s2);
    cudaGetSymbolAddress(&plg, g_lg);
    float* xl = (float*)pxl; float* xr = (float*)pxr;
    float* h  = (float*)ph;  float* h2 = (float*)ph2;
    float* s1 = (float*)ps1; float* s2 = (float*)ps2;
    float* lg = (float*)plg;

    const int tb = 256;
    // ---- CSR build (same graph reused by all 4 GAT layers) ----
    cudaMemsetAsync(pc, 0, (size_t)(M + 1) * sizeof(int));
    int gE = (ET + tb - 1) / tb; if (gE > 4096) gE = 4096;
    k_hist<<<gE, tb>>>(ei + E, E, M);
    k_scan<<<1, 1024>>>(M);
    k_scatter<<<gE, tb>>>(ei, ei + E, E, M);
    k_sortseg2<<<(M + SORT_NODES - 1) / SORT_NODES, SORT_NODES>>>(M);

    // ---- GEMM config ----
    size_t smem2 = (size_t)4 * 128 * LDB * sizeof(__nv_bfloat16);  // 139264
    cudaFuncSetAttribute(k_gemm2_bf16, cudaFuncAttributeMaxDynamicSharedMemorySize, (int)smem2);
    int gg = (M + 127) / 128;
    int gw = (M * 32 + tb - 1) / tb;
    int g32 = (M + 31) / 32;

    // ---- actor path ----
    k_gemm2_bf16<<<gg, tb, smem2>>>(x, Wp[0][0], Wp[0][1], xl, Wp[0][2], Wp[0][3], xr, M);
    k_gat128<<<gw, tb>>>(xl, xr, Wp[0][4], Wp[0][5], h, M, 0.01f);
    k_gemm7x2<<<g32, tb>>>(h, Wp[1][0], Wp[1][1], Wp[1][2], Wp[1][3], s1, s2, M);
    k_gat7<<<gw, tb>>>(s1, s2, Wp[1][4], Wp[1][5], lg, M);
    k_actor<<<1, 32>>>(lg, gu, out, B, N);

    // ---- critic path ----
    k_gemm2_bf16<<<gg, tb, smem2>>>(x, Wp[2][0], Wp[2][1], xl, Wp[2][2], Wp[2][3], xr, M);
    k_gat128<<<gw, tb>>>(xl, xr, Wp[2][4], Wp[2][5], h2, M, 0.01f);
    k_gemm2_bf16<<<gg, tb, smem2>>>(h2, Wp[3][0], Wp[3][1], xl, Wp[3][2], Wp[3][3], xr, M);
    k_gat128<<<gw, tb>>>(xl, xr, Wp[3][4], Wp[3][5], h, M, 0.f);
    k_value<<<gw, tb>>>(h, fcW, fcb, out + 2 * B * NC * NS, M);
}